// round 9
// baseline (speedup 1.0000x reference)
#include <cuda_runtime.h>
#include <cuda_fp16.h>

#define NN   100000
#define EE   1600000
#define KDIM 128
#define ODIM 128      // H*D = 4*32
#define ALPHA 0.2f
#define NBLK_SCAN ((NN + 1023) / 1024)   // 98

// -------- device scratch (no allocations allowed) --------
__device__ __half  g_ft16[(size_t)NN * ODIM];  // 25.6 MB, fp16 messages
__device__ float   g_al[NN];
__device__ float   g_ar[NN];
__device__ int     g_cnt[NN];
__device__ int     g_off[NN];
__device__ int     g_cur[NN];
__device__ int     g_bsum[128];
__device__ float2  g_pair[EE];                 // (src-as-bits, exp(e)) grouped by dst

// -------- helpers ----------------------------------------------------------
__device__ __forceinline__ float f16hi(float x) {
    return __half2float(__float2half_rn(x));
}
__device__ __forceinline__ unsigned packh2(float e, float o) {
    __half2 h = __floats2half2_rn(e, o);   // e -> lower 16 (first k of pair)
    return *(unsigned*)&h;
}
__device__ __forceinline__ void mma16816(float* acc, const unsigned* a,
                                         unsigned b0, unsigned b1) {
    asm("mma.sync.aligned.m16n8k16.row.col.f32.f16.f16.f32 "
        "{%0,%1,%2,%3}, {%4,%5,%6,%7}, {%8,%9}, {%0,%1,%2,%3};"
        : "+f"(acc[0]), "+f"(acc[1]), "+f"(acc[2]), "+f"(acc[3])
        : "r"(a[0]), "r"(a[1]), "r"(a[2]), "r"(a[3]), "r"(b0), "r"(b1));
}

// -------- K0: reset per-node counters --------------------------------------
__global__ void k_init() {
    int i = blockIdx.x * blockDim.x + threadIdx.x;
    if (i < NN) g_cnt[i] = 0;
}

// -------- K1: ft = X @ W via fp16x3 tensor-core mma -------------------------
// Grid (782, 2): blockIdx.x = 128-row tile, blockIdx.y = 64-col tile.
// W staged in smem, hi/lo interleaved uint2, XOR-swizzled for conflict-free
// B-fragment LDS.64. A loaded from global fp32, split hi/lo in registers.
// nb==0 blocks fuse the head-0 attention-score reduction (cols 0..31).
__global__ __launch_bounds__(256)
void k_gemm_tc(const float* __restrict__ A, const float* __restrict__ W,
               const float* __restrict__ attn_l, const float* __restrict__ attn_r) {
    // sW[n_local*64 + (kk ^ ((n_local&7)<<2))] = {hi-pair, lo-pair}
    __shared__ uint2 sW[64 * 64];          // 32 KB

    const int tid  = threadIdx.x;
    const int lane = tid & 31;
    const int warp = tid >> 5;             // 0..7
    const int g    = lane >> 2;            // 0..7
    const int c    = lane & 3;             // 0..3
    const int nb   = blockIdx.y;           // 0..1 (col tile)
    const int ncol0 = nb * 64;

    // ---- stage W tile (all k, 64 cols) into smem, split fp16 hi/lo ----
    for (int idx = tid; idx < 4096; idx += 256) {
        int nl = idx & 63;                 // coalesced over n
        int kk = idx >> 6;                 // k-pair index 0..63
        float e = W[(size_t)(2 * kk) * ODIM + ncol0 + nl];
        float o = W[(size_t)(2 * kk + 1) * ODIM + ncol0 + nl];
        float eh = f16hi(e), oh = f16hi(o);
        sW[nl * 64 + (kk ^ ((nl & 7) << 2))] =
            make_uint2(packh2(eh, oh), packh2(e - eh, o - oh));
    }
    __syncthreads();

    const int rA = blockIdx.x * 128 + warp * 16 + g;
    const int rB = rA + 8;
    const bool vA = rA < NN, vB = rB < NN;
    const float* pA = A + (size_t)rA * KDIM;
    const float* pB = A + (size_t)rB * KDIM;

    float acc[8][4];
#pragma unroll
    for (int t = 0; t < 8; t++)
#pragma unroll
        for (int j = 0; j < 4; j++) acc[t][j] = 0.f;

    const int xr = (g << 2);               // per-thread XOR swizzle

#pragma unroll
    for (int ks = 0; ks < 8; ks++) {
        const int k0 = ks * 16;
        float2 f0 = vA ? *(const float2*)(pA + k0 + 2 * c)     : make_float2(0.f, 0.f);
        float2 f2 = vA ? *(const float2*)(pA + k0 + 2 * c + 8) : make_float2(0.f, 0.f);
        float2 f1 = vB ? *(const float2*)(pB + k0 + 2 * c)     : make_float2(0.f, 0.f);
        float2 f3 = vB ? *(const float2*)(pB + k0 + 2 * c + 8) : make_float2(0.f, 0.f);

        unsigned ah[4], al_[4];
        {
            float hx, hy;
            hx = f16hi(f0.x); hy = f16hi(f0.y);
            ah[0] = packh2(hx, hy); al_[0] = packh2(f0.x - hx, f0.y - hy);
            hx = f16hi(f1.x); hy = f16hi(f1.y);
            ah[1] = packh2(hx, hy); al_[1] = packh2(f1.x - hx, f1.y - hy);
            hx = f16hi(f2.x); hy = f16hi(f2.y);
            ah[2] = packh2(hx, hy); al_[2] = packh2(f2.x - hx, f2.y - hy);
            hx = f16hi(f3.x); hy = f16hi(f3.y);
            ah[3] = packh2(hx, hy); al_[3] = packh2(f3.x - hx, f3.y - hy);
        }

        const int kk0 = (ks * 8 + c) ^ xr;
        const int kk1 = (ks * 8 + 4 + c) ^ xr;
#pragma unroll
        for (int t = 0; t < 8; t++) {
            uint2 B0 = sW[(t * 8 + g) * 64 + kk0];
            uint2 B1 = sW[(t * 8 + g) * 64 + kk1];
            mma16816(acc[t], ah,  B0.x, B1.x);   // hiA * hiW
            mma16816(acc[t], ah,  B0.y, B1.y);   // hiA * loW
            mma16816(acc[t], al_, B0.x, B1.x);   // loA * hiW
        }
    }

    // ---- epilogue 1: fp16 messages (64 cols of this block) ----
#pragma unroll
    for (int t = 0; t < 8; t++) {
        int col = ncol0 + t * 8 + 2 * c;
        if (vA) *(unsigned*)(g_ft16 + ((size_t)rA << 7) + col) =
            packh2(acc[t][0], acc[t][1]);
        if (vB) *(unsigned*)(g_ft16 + ((size_t)rB << 7) + col) =
            packh2(acc[t][2], acc[t][3]);
    }

    // ---- epilogue 2: head-0 scores (cols 0..31 = tiles 0..3 of nb==0) ----
    if (nb == 0) {
        float pl0 = 0.f, pr0 = 0.f, pl1 = 0.f, pr1 = 0.f;
#pragma unroll
        for (int t = 0; t < 4; t++) {
            float le = attn_l[8 * t + 2 * c], lo_ = attn_l[8 * t + 2 * c + 1];
            float re = attn_r[8 * t + 2 * c], ro  = attn_r[8 * t + 2 * c + 1];
            pl0 += acc[t][0] * le + acc[t][1] * lo_;
            pr0 += acc[t][0] * re + acc[t][1] * ro;
            pl1 += acc[t][2] * le + acc[t][3] * lo_;
            pr1 += acc[t][2] * re + acc[t][3] * ro;
        }
#pragma unroll
        for (int o = 1; o <= 2; o <<= 1) {
            pl0 += __shfl_xor_sync(0xffffffffu, pl0, o);
            pr0 += __shfl_xor_sync(0xffffffffu, pr0, o);
            pl1 += __shfl_xor_sync(0xffffffffu, pl1, o);
            pr1 += __shfl_xor_sync(0xffffffffu, pr1, o);
        }
        if (c == 0) {
            if (vA) { g_al[rA] = pl0; g_ar[rA] = pr0; }
            if (vB) { g_al[rB] = pl1; g_ar[rB] = pr1; }
        }
    }
}

// -------- K3: histogram of dst ---------------------------------------------
__global__ void k_hist(const int* __restrict__ dst) {
    int i = blockIdx.x * blockDim.x + threadIdx.x;
    if (i < EE) atomicAdd(&g_cnt[dst[i]], 1);
}

// -------- K4a: per-block exclusive scan of counts --------------------------
__global__ __launch_bounds__(1024)
void k_scan1() {
    __shared__ int sh[1024];
    int tid = threadIdx.x;
    int i = blockIdx.x * 1024 + tid;
    int v = (i < NN) ? g_cnt[i] : 0;
    sh[tid] = v;
    __syncthreads();
#pragma unroll
    for (int o = 1; o < 1024; o <<= 1) {
        int t = (tid >= o) ? sh[tid - o] : 0;
        __syncthreads();
        sh[tid] += t;
        __syncthreads();
    }
    if (i < NN) g_off[i] = sh[tid] - v;          // exclusive
    if (tid == 1023) g_bsum[blockIdx.x] = sh[1023];
}

// -------- K4b: serial scan of 98 block sums --------------------------------
__global__ void k_scan2() {
    if (threadIdx.x == 0 && blockIdx.x == 0) {
        int run = 0;
        for (int b = 0; b < NBLK_SCAN; b++) {
            int t = g_bsum[b];
            g_bsum[b] = run;
            run += t;
        }
    }
}

// -------- K4c: add block offsets + init scatter cursors --------------------
__global__ void k_scan3() {
    int i = blockIdx.x * blockDim.x + threadIdx.x;
    if (i < NN) {
        int o = g_off[i] + g_bsum[i >> 10];
        g_off[i] = o;
        g_cur[i] = o;
    }
}

// -------- K5: fused edge pass: logits, exp, scatter-sort -------------------
__global__ void k_edge(const int* __restrict__ src, const int* __restrict__ dst) {
    int i = blockIdx.x * blockDim.x + threadIdx.x;
    if (i >= EE) return;
    int s = src[i];
    int d = dst[i];
    float e = g_al[s] + g_ar[d];
    e = (e > 0.f) ? e : ALPHA * e;
    float ex = __expf(e);           // |e| <~ 10: safe without max-shift
    int pos = atomicAdd(&g_cur[d], 1);
    g_pair[pos] = make_float2(__int_as_float(s), ex);
}

// -------- K6: aggregation, warp per dst node, fp16 messages ----------------
__global__ __launch_bounds__(256)
void k_agg(float* __restrict__ out) {
    int node = blockIdx.x * 8 + (threadIdx.x >> 5);
    int lane = threadIdx.x & 31;
    if (node >= NN) return;
    int beg = g_off[node];
    int cnt = g_cnt[node];

    // pass 1: denominator (lane-parallel, coalesced)
    float sum = 0.f;
    for (int k = lane; k < cnt; k += 32) sum += g_pair[beg + k].y;
#pragma unroll
    for (int o = 16; o; o >>= 1) sum += __shfl_xor_sync(0xffffffffu, sum, o);
    float inv = (cnt > 0) ? __frcp_rn(sum) : 0.f;

    // pass 2: weighted gather-accumulate (fp16 messages, fp32 accum)
    float4 acc = make_float4(0.f, 0.f, 0.f, 0.f);
    float2 p_n = (cnt > 0) ? g_pair[beg] : make_float2(0.f, 0.f);
    for (int k = 0; k < cnt; k++) {
        float2 p = p_n;
        if (k + 1 < cnt) p_n = g_pair[beg + k + 1];
        int   s  = __float_as_int(p.x);
        float cc = p.y * inv;
        uint2 u = *(const uint2*)(g_ft16 + ((size_t)s << 7) + (lane << 2));
        float2 f0 = __half22float2(*(__half2*)&u.x);
        float2 f1 = __half22float2(*(__half2*)&u.y);
        acc.x += cc * f0.x;
        acc.y += cc * f0.y;
        acc.z += cc * f1.x;
        acc.w += cc * f1.y;
    }
    *(float4*)(out + ((size_t)node << 7) + (lane << 2)) = acc;
}

// ---------------------------------------------------------------------------
extern "C" void kernel_launch(void* const* d_in, const int* in_sizes, int n_in,
                              void* d_out, int out_size) {
    const float* inputs = (const float*)d_in[0];
    const int*   src    = (const int*)d_in[1];
    const int*   dst    = (const int*)d_in[2];
    const float* fc_w   = (const float*)d_in[3];
    const float* attn_l = (const float*)d_in[4];
    const float* attn_r = (const float*)d_in[5];
    float* out = (float*)d_out;

    dim3 ggrid((NN + 127) / 128, 2);
    k_init   <<<(NN + 255) / 256, 256>>>();
    k_gemm_tc<<<ggrid, 256>>>(inputs, fc_w, attn_l, attn_r);
    k_hist   <<<(EE + 255) / 256, 256>>>(dst);
    k_scan1  <<<NBLK_SCAN, 1024>>>();
    k_scan2  <<<1, 32>>>();
    k_scan3  <<<(NN + 255) / 256, 256>>>();
    k_edge   <<<(EE + 255) / 256, 256>>>(src, dst);
    k_agg    <<<(NN + 7) / 8, 256>>>(out);
}

// round 13
// speedup vs baseline: 1.2781x; 1.2781x over previous
#include <cuda_runtime.h>
#include <cuda_fp16.h>

#define NN   100000
#define EE   1600000
#define KDIM 128
#define ODIM 128      // H*D = 4*32
#define ALPHA 0.2f
#define NBLK_SCAN ((NN + 1023) / 1024)   // 98

// -------- device scratch (no allocations allowed) --------
__device__ __half  g_ft16[(size_t)NN * ODIM];  // 25.6 MB, fp16 messages
__device__ float   g_al[NN];
__device__ float   g_ar[NN];
__device__ int     g_cnt[NN];
__device__ int     g_off[NN];
__device__ int     g_cur[NN];
__device__ int     g_bsum[128];
__device__ float2  g_pair[EE];                 // (src-as-bits, exp(e)) grouped by dst

// -------- packed f32x2 helpers (plain Blackwell, NOT 'a'-gated) -------------
__device__ __forceinline__ void fma2(unsigned long long& acc,
                                     unsigned long long a, unsigned long long b) {
    asm("fma.rn.f32x2 %0, %1, %2, %3;" : "=l"(acc) : "l"(a), "l"(b), "l"(acc));
}
__device__ __forceinline__ unsigned long long packdup(float x) {
    unsigned long long r;
    unsigned u = __float_as_uint(x);
    asm("mov.b64 %0, {%1, %2};" : "=l"(r) : "r"(u), "r"(u));
    return r;
}
__device__ __forceinline__ void unpack2(unsigned long long v, float& lo, float& hi) {
    unsigned a, b;
    asm("mov.b64 {%0, %1}, %2;" : "=r"(a), "=r"(b) : "l"(v));
    lo = __uint_as_float(a);
    hi = __uint_as_float(b);
}

// -------- K0: reset per-node counters --------------------------------------
__global__ void k_init() {
    int i = blockIdx.x * blockDim.x + threadIdx.x;
    if (i < NN) g_cnt[i] = 0;
}

// -------- K1: ft = X @ W via packed FFMA2 (f32x2) + fused head-0 scores -----
// As is staged column-major so row-pairs load as one broadcast LDS.64.
// 16 fma.rn.f32x2 per k per thread = 32 fp32 MACs (2x the FFMA rate).
__global__ __launch_bounds__(256)
void k_gemm(const float* __restrict__ A, const float* __restrict__ W,
            const float* __restrict__ attn_l, const float* __restrict__ attn_r) {
    __shared__ __align__(16) float As[64 * 66];   // col-major: As[k*66 + r], 16.5 KB
    __shared__ float Bs[64 * 128];                // 32 KB
    const int tid = threadIdx.x;
    const int tx = tid & 31;     // 32 col-groups of 4
    const int ty = tid >> 5;     // 8 row-groups of 8 (== warp id)
    const int row0 = blockIdx.x * 64;

    unsigned long long acc2[4][4];   // [row-pair][col] packed {row 2rp, row 2rp+1}
#pragma unroll
    for (int rp = 0; rp < 4; rp++)
#pragma unroll
        for (int j = 0; j < 4; j++) acc2[rp][j] = 0ull;

    for (int kt = 0; kt < 2; kt++) {
        // stage A tile 64 rows x 64 k, col-major (coalesced global reads)
#pragma unroll
        for (int p = 0; p < 4; p++) {
            int i = tid + p * 256;
            int r = i >> 4, c4 = i & 15;
            int grow = row0 + r;
            float4 v = make_float4(0.f, 0.f, 0.f, 0.f);
            if (grow < NN)
                v = *(const float4*)(A + (size_t)grow * KDIM + kt * 64 + c4 * 4);
            As[(c4 * 4 + 0) * 66 + r] = v.x;
            As[(c4 * 4 + 1) * 66 + r] = v.y;
            As[(c4 * 4 + 2) * 66 + r] = v.z;
            As[(c4 * 4 + 3) * 66 + r] = v.w;
        }
        // stage W tile 64 k x 128 cols
#pragma unroll
        for (int p = 0; p < 8; p++) {
            int i = tid + p * 256;
            int r = i >> 5, c4 = i & 31;
            *(float4*)(Bs + r * 128 + c4 * 4) =
                *(const float4*)(W + (size_t)(kt * 64 + r) * ODIM + c4 * 4);
        }
        __syncthreads();
#pragma unroll 8
        for (int k = 0; k < 64; k++) {
            float4 b = *(float4*)(Bs + k * 128 + tx * 4);
            unsigned long long bxx = packdup(b.x);
            unsigned long long byy = packdup(b.y);
            unsigned long long bzz = packdup(b.z);
            unsigned long long bww = packdup(b.w);
            const float* ak = As + k * 66 + ty * 8;
#pragma unroll
            for (int rp = 0; rp < 4; rp++) {
                unsigned long long a2 =
                    *(const unsigned long long*)(ak + 2 * rp);  // {row2rp, row2rp+1}
                fma2(acc2[rp][0], a2, bxx);
                fma2(acc2[rp][1], a2, byy);
                fma2(acc2[rp][2], a2, bzz);
                fma2(acc2[rp][3], a2, bww);
            }
        }
        __syncthreads();
    }

    // unpack to per-row accumulators (lo lane = even row)
    float acc[8][4];
#pragma unroll
    for (int rp = 0; rp < 4; rp++)
#pragma unroll
        for (int j = 0; j < 4; j++)
            unpack2(acc2[rp][j], acc[2 * rp][j], acc[2 * rp + 1][j]);

    // ---- epilogue 1: fp16 messages ----
#pragma unroll
    for (int r = 0; r < 8; r++) {
        int grow = row0 + ty * 8 + r;
        if (grow < NN) {
            __half2 h0 = __floats2half2_rn(acc[r][0], acc[r][1]);
            __half2 h1 = __floats2half2_rn(acc[r][2], acc[r][3]);
            uint2 u;
            u.x = *(unsigned*)&h0;
            u.y = *(unsigned*)&h1;
            *(uint2*)(g_ft16 + ((size_t)grow << 7) + tx * 4) = u;
        }
    }

    // ---- epilogue 2: head-0 scores (cols 0..31 live in lanes tx 0..7) ----
    float pl[8], pr[8];
    {
        int base = (tx & 7) * 4;
        float l0 = attn_l[base + 0], l1 = attn_l[base + 1];
        float l2 = attn_l[base + 2], l3 = attn_l[base + 3];
        float r0 = attn_r[base + 0], r1 = attn_r[base + 1];
        float r2 = attn_r[base + 2], r3 = attn_r[base + 3];
        bool active = (tx < 8);
#pragma unroll
        for (int r = 0; r < 8; r++) {
            float a = active ? (acc[r][0] * l0 + acc[r][1] * l1 +
                                acc[r][2] * l2 + acc[r][3] * l3) : 0.f;
            float b = active ? (acc[r][0] * r0 + acc[r][1] * r1 +
                                acc[r][2] * r2 + acc[r][3] * r3) : 0.f;
            pl[r] = a; pr[r] = b;
        }
    }
#pragma unroll
    for (int o = 1; o <= 4; o <<= 1) {
#pragma unroll
        for (int r = 0; r < 8; r++) {
            pl[r] += __shfl_xor_sync(0xffffffffu, pl[r], o);
            pr[r] += __shfl_xor_sync(0xffffffffu, pr[r], o);
        }
    }
    if (tx == 0) {
#pragma unroll
        for (int r = 0; r < 8; r++) {
            int grow = row0 + ty * 8 + r;
            if (grow < NN) { g_al[grow] = pl[r]; g_ar[grow] = pr[r]; }
        }
    }
}

// -------- K3: histogram of dst ---------------------------------------------
__global__ void k_hist(const int* __restrict__ dst) {
    int i = blockIdx.x * blockDim.x + threadIdx.x;
    if (i < EE) atomicAdd(&g_cnt[dst[i]], 1);
}

// -------- K4a: per-block exclusive scan of counts --------------------------
__global__ __launch_bounds__(1024)
void k_scan1() {
    __shared__ int sh[1024];
    int tid = threadIdx.x;
    int i = blockIdx.x * 1024 + tid;
    int v = (i < NN) ? g_cnt[i] : 0;
    sh[tid] = v;
    __syncthreads();
#pragma unroll
    for (int o = 1; o < 1024; o <<= 1) {
        int t = (tid >= o) ? sh[tid - o] : 0;
        __syncthreads();
        sh[tid] += t;
        __syncthreads();
    }
    if (i < NN) g_off[i] = sh[tid] - v;          // exclusive
    if (tid == 1023) g_bsum[blockIdx.x] = sh[1023];
}

// -------- K4b: serial scan of 98 block sums --------------------------------
__global__ void k_scan2() {
    if (threadIdx.x == 0 && blockIdx.x == 0) {
        int run = 0;
        for (int b = 0; b < NBLK_SCAN; b++) {
            int t = g_bsum[b];
            g_bsum[b] = run;
            run += t;
        }
    }
}

// -------- K4c: add block offsets + init scatter cursors --------------------
__global__ void k_scan3() {
    int i = blockIdx.x * blockDim.x + threadIdx.x;
    if (i < NN) {
        int o = g_off[i] + g_bsum[i >> 10];
        g_off[i] = o;
        g_cur[i] = o;
    }
}

// -------- K5: fused edge pass: logits, exp, scatter-sort -------------------
__global__ void k_edge(const int* __restrict__ src, const int* __restrict__ dst) {
    int i = blockIdx.x * blockDim.x + threadIdx.x;
    if (i >= EE) return;
    int s = src[i];
    int d = dst[i];
    float e = g_al[s] + g_ar[d];
    e = (e > 0.f) ? e : ALPHA * e;
    float ex = __expf(e);           // |e| <~ 10: safe without max-shift
    int pos = atomicAdd(&g_cur[d], 1);
    g_pair[pos] = make_float2(__int_as_float(s), ex);
}

// -------- K6: aggregation, warp per dst node, fp16 messages ----------------
__global__ __launch_bounds__(256)
void k_agg(float* __restrict__ out) {
    int node = blockIdx.x * 8 + (threadIdx.x >> 5);
    int lane = threadIdx.x & 31;
    if (node >= NN) return;
    int beg = g_off[node];
    int cnt = g_cnt[node];

    // pass 1: denominator (lane-parallel, coalesced)
    float sum = 0.f;
    for (int k = lane; k < cnt; k += 32) sum += g_pair[beg + k].y;
#pragma unroll
    for (int o = 16; o; o >>= 1) sum += __shfl_xor_sync(0xffffffffu, sum, o);
    float inv = (cnt > 0) ? __frcp_rn(sum) : 0.f;

    // pass 2: weighted gather-accumulate (fp16 messages, fp32 accum)
    float4 acc = make_float4(0.f, 0.f, 0.f, 0.f);
    float2 p_n = (cnt > 0) ? g_pair[beg] : make_float2(0.f, 0.f);
    for (int k = 0; k < cnt; k++) {
        float2 p = p_n;
        if (k + 1 < cnt) p_n = g_pair[beg + k + 1];
        int   s  = __float_as_int(p.x);
        float cc = p.y * inv;
        uint2 u = *(const uint2*)(g_ft16 + ((size_t)s << 7) + (lane << 2));
        float2 f0 = __half22float2(*(__half2*)&u.x);
        float2 f1 = __half22float2(*(__half2*)&u.y);
        acc.x += cc * f0.x;
        acc.y += cc * f0.y;
        acc.z += cc * f1.x;
        acc.w += cc * f1.y;
    }
    *(float4*)(out + ((size_t)node << 7) + (lane << 2)) = acc;
}

// ---------------------------------------------------------------------------
extern "C" void kernel_launch(void* const* d_in, const int* in_sizes, int n_in,
                              void* d_out, int out_size) {
    const float* inputs = (const float*)d_in[0];
    const int*   src    = (const int*)d_in[1];
    const int*   dst    = (const int*)d_in[2];
    const float* fc_w   = (const float*)d_in[3];
    const float* attn_l = (const float*)d_in[4];
    const float* attn_r = (const float*)d_in[5];
    float* out = (float*)d_out;

    k_init <<<(NN + 255) / 256, 256>>>();
    k_gemm <<<(NN + 63) / 64, 256>>>(inputs, fc_w, attn_l, attn_r);
    k_hist <<<(EE + 255) / 256, 256>>>(dst);
    k_scan1<<<NBLK_SCAN, 1024>>>();
    k_scan2<<<1, 32>>>();
    k_scan3<<<(NN + 255) / 256, 256>>>();
    k_edge <<<(EE + 255) / 256, 256>>>(src, dst);
    k_agg  <<<(NN + 7) / 8, 256>>>(out);
}